// round 12
// baseline (speedup 1.0000x reference)
#include <cuda_runtime.h>
#include <cuda_fp16.h>

// Bilinear flow warp. input1: [B,C,H,W] fp32, flow: [B,2,H,W] fp32.
// Fixed shapes: B=8, C=64, H=256, W=448.
//
// Pass A: NCHW fp32 -> NHWC fp16 scratch (R10 version: measured fastest).
// Pass B: 4-corner gather (corner = 64 contiguous fp16 ch = 128B), MLP=8
//         batched LDGs, uint4 weight/offset LDS, half2 FMA blend, chunk-major
//         fp16 result tile, wide NCHW fp32 writeback.
//         Phase 1: ONE thread per pixel (computes all 4 corners, 2x STS.128)
//         -> no redundant flow loads / weight stores.

#define B_   8
#define C_   64
#define H_   256
#define W_   448
#define HW_  (H_ * W_)            // 114688
#define CHW_ (C_ * HW_)           // 7340032
#define TILES_PER_B (HW_ / 64)    // 1792 (W=448 divisible by 64: tile stays in one row)

// ~117 MB scratch: input in NHWC fp16 layout [B, H, W, C]
__device__ static __half g_nhwc[(size_t)B_ * HW_ * C_];

static __device__ __forceinline__ unsigned int h2bits(__half2 h) {
    return *(unsigned int*)&h;
}
static __device__ __forceinline__ __half2 bits2h(unsigned int u) {
    return *(__half2*)&u;
}

// ---------------------------------------------------------------------------
// Kernel A: NCHW fp32 -> NHWC fp16.  Tile = 64 ch x 64 px, 256 threads.
// ---------------------------------------------------------------------------
__global__ void __launch_bounds__(256) nchw_to_nhwc_f16(const float* __restrict__ in)
{
    __shared__ float sm[64 * 65];    // [c][px], row stride 65

    int blk  = blockIdx.x;
    int b    = blk / TILES_PER_B;
    int tile = blk - b * TILES_PER_B;
    int px0  = tile * 64;
    int tid  = threadIdx.x;

    // ---- load: float4 per thread (16 threads cover one channel row of 64 px) ----
    {
        int c_lo = tid >> 4;             // 0..15
        int px4  = (tid & 15) * 4;       // 0..60
        const float* src = in + b * CHW_ + px0 + px4;
        #pragma unroll
        for (int it = 0; it < 4; ++it) {
            int c = it * 16 + c_lo;
            float4 v = *(const float4*)(src + c * HW_);
            float* s = sm + c * 65 + px4;
            s[0] = v.x; s[1] = v.y; s[2] = v.z; s[3] = v.w;
        }
    }
    __syncthreads();

    // ---- store: 2048 half2 words (64 px x 32 words); 8 words per thread.
    //      Consecutive tid -> consecutive words: full 128B store wavefronts. ----
    {
        unsigned int* dst = (unsigned int*)(g_nhwc + (size_t)(b * HW_ + px0) * 64);
        #pragma unroll
        for (int k = 0; k < 8; ++k) {
            int idx = k * 256 + tid;
            int px  = idx >> 5;          // 0..63
            int cw  = idx & 31;          // channel word: channels 2cw, 2cw+1
            float a0 = sm[(2 * cw)     * 65 + px];
            float a1 = sm[(2 * cw + 1) * 65 + px];
            __half2 h = __floats2half2_rn(a0, a1);
            dst[px * 32 + cw] = *(unsigned int*)&h;
        }
    }
}

// ---------------------------------------------------------------------------
// Kernel B: gather from NHWC fp16, write NCHW fp32.
// Block = 256 threads handles 64 consecutive pixels (one row) x 64 channels.
// ---------------------------------------------------------------------------
__global__ void __launch_bounds__(256, 8) warp_gather_f16(
    const float* __restrict__ flow,   // [B,2,H,W]
    float* __restrict__ out)          // [B,C,H,W]
{
    __shared__ alignas(16) __half2 s_wh[64][4];  // per-pixel corner weights (half2-bcast)
    __shared__ alignas(16) int     s_o[64][4];   // per-pixel corner base offsets (half idx)
    __shared__ __half2 s_r2[32 * 66];            // result tile [cw][px], stride 66

    int blk  = blockIdx.x;
    int b    = blk / TILES_PER_B;
    int tile = blk - b * TILES_PER_B;
    int rem0 = tile * 64;
    int tid  = threadIdx.x;

    // ---- phase 1: ONE thread per pixel; all 4 corners; 2x STS.128 ----
    if (tid < 64) {
        int px  = tid;
        int rem = rem0 + px;
        int h   = rem / W_;
        int w   = rem - h * W_;

        const float* fl = flow + b * 2 * HW_ + rem;
        float fx = __ldg(fl);
        float fy = __ldg(fl + HW_);

        float x = (float)w + fx;
        float y = (float)h + fy;

        float x0f = floorf(x);
        float y0f = floorf(y);
        int x0 = (int)x0f;
        int y0 = (int)y0f;
        int x1 = x0 + 1;
        int y1 = y0 + 1;

        float wx1 = x - x0f;
        float wx0 = 1.0f - wx1;
        float wy1 = y - y0f;
        float wy0 = 1.0f - wy1;

        float vx0 = (x0 >= 0 && x0 < W_) ? 1.0f : 0.0f;
        float vx1 = (x1 >= 0 && x1 < W_) ? 1.0f : 0.0f;
        float vy0 = (y0 >= 0 && y0 < H_) ? 1.0f : 0.0f;
        float vy1 = (y1 >= 0 && y1 < H_) ? 1.0f : 0.0f;

        int x0c = min(max(x0, 0), W_ - 1);
        int x1c = min(max(x1, 0), W_ - 1);
        int y0c = min(max(y0, 0), H_ - 1);
        int y1c = min(max(y1, 0), H_ - 1);

        uint4 wq;
        wq.x = h2bits(__float2half2_rn(wy0 * wx0 * vy0 * vx0));
        wq.y = h2bits(__float2half2_rn(wy0 * wx1 * vy0 * vx1));
        wq.z = h2bits(__float2half2_rn(wy1 * wx0 * vy1 * vx0));
        wq.w = h2bits(__float2half2_rn(wy1 * wx1 * vy1 * vx1));

        int row0 = (b * H_ + y0c) * W_;
        int row1 = (b * H_ + y1c) * W_;
        uint4 oq;
        oq.x = (unsigned int)((row0 + x0c) * 64);
        oq.y = (unsigned int)((row0 + x1c) * 64);
        oq.z = (unsigned int)((row1 + x0c) * 64);
        oq.w = (unsigned int)((row1 + x1c) * 64);

        *(uint4*)(&s_wh[px][0]) = wq;
        *(uint4*)(&s_o[px][0])  = oq;
    }
    __syncthreads();

    // ---- phase 2: 8 warps x 8 pixels; lane covers channels (2*lane, 2*lane+1).
    //      MLP=8 (2 px x 4 corners), uint4 offset/weight loads, half2 blend,
    //      chunk-major STS (2-way max). ----
    {
        int wid  = tid >> 5;
        int lane = tid & 31;

        #pragma unroll
        for (int hblk = 0; hblk < 4; ++hblk) {
            int pbase = wid * 8 + hblk * 2;

            __half2 v[2][4];
            #pragma unroll
            for (int j = 0; j < 2; ++j) {
                uint4 ov = *(const uint4*)(&s_o[pbase + j][0]);   // 1 LDS.128
                v[j][0] = __ldg((const __half2*)(g_nhwc + (int)ov.x) + lane);
                v[j][1] = __ldg((const __half2*)(g_nhwc + (int)ov.y) + lane);
                v[j][2] = __ldg((const __half2*)(g_nhwc + (int)ov.z) + lane);
                v[j][3] = __ldg((const __half2*)(g_nhwc + (int)ov.w) + lane);
            }

            #pragma unroll
            for (int j = 0; j < 2; ++j) {
                int p = pbase + j;
                uint4 wv = *(const uint4*)(&s_wh[p][0]);          // 1 LDS.128
                __half2 r = __hfma2(v[j][0], bits2h(wv.x),
                            __hfma2(v[j][1], bits2h(wv.y),
                            __hfma2(v[j][2], bits2h(wv.z),
                            __hmul2(v[j][3], bits2h(wv.w)))));
                s_r2[lane * 66 + p] = r;
            }
        }
    }
    __syncthreads();

    // ---- phase 3: wide NCHW fp32 writeback.
    //      Warp handles 4 cw rows; lane = pixel pair: LDS.64 + 2x STG.64. ----
    {
        int wid  = tid >> 5;
        int lane = tid & 31;
        float* dst = out + b * CHW_ + rem0;
        #pragma unroll
        for (int i = 0; i < 4; ++i) {
            int cw = wid * 4 + i;
            uint2 hh = *(const uint2*)&s_r2[cw * 66 + 2 * lane];  // px 2l, 2l+1
            float2 f0 = __half22float2(bits2h(hh.x));   // (ch 2cw, 2cw+1) @ px 2l
            float2 f1 = __half22float2(bits2h(hh.y));   // (ch 2cw, 2cw+1) @ px 2l+1
            *(float2*)(dst + (2 * cw)     * HW_ + 2 * lane) = make_float2(f0.x, f1.x);
            *(float2*)(dst + (2 * cw + 1) * HW_ + 2 * lane) = make_float2(f0.y, f1.y);
        }
    }
}

extern "C" void kernel_launch(void* const* d_in, const int* in_sizes, int n_in,
                              void* d_out, int out_size)
{
    const float* img  = (const float*)d_in[0];
    const float* flow = (const float*)d_in[1];
    float* out = (float*)d_out;

    const int blocks = B_ * TILES_PER_B;   // 14336
    nchw_to_nhwc_f16<<<blocks, 256>>>(img);
    warp_gather_f16<<<blocks, 256>>>(flow, out);
}